// round 15
// baseline (speedup 1.0000x reference)
#include <cuda_runtime.h>
#include <cuda_fp16.h>
#include <math.h>
#include <stdint.h>
#include <string.h>

#define Bb 32
#define Cc 256
#define Tt 4096
#define Hh 512
#define BHALF 16

// ---- scratch (static device globals; no runtime allocation) ----
__device__ __half g_yln_h[(size_t)Bb * Tt * Cc];   // conv+LN output (B,T,C) fp16
__device__ __half g_y1_h[(size_t)Bb * Tt * Hh];    // GELU(pw1) output (B,T,H) fp16
__device__ __half g_w1h[(size_t)Hh * Cc];          // pw1_w fp16
__device__ __half g_w2s[(size_t)Bb * Cc * Hh];     // pw2_w * s[b,h] fp16 per batch
__device__ float  g_gx2[Bb * Hh];                  // sum of squares per (b,h)
__device__ float  g_biasC[Cc];                     // pw2_b + pw2_w @ beta

// ---- streams/events created at load time ----
struct StreamPack {
    cudaStream_t s1;
    cudaEvent_t eFork, eJoin;
    StreamPack() {
        cudaStreamCreateWithFlags(&s1, cudaStreamNonBlocking);
        cudaEventCreateWithFlags(&eFork, cudaEventDisableTiming);
        cudaEventCreateWithFlags(&eJoin, cudaEventDisableTiming);
    }
};
static StreamPack g_sp;

// ============================================================
// helpers
// ============================================================
__device__ __forceinline__ uint32_t smem_u32(const void* p) {
    uint32_t a;
    asm("{ .reg .u64 t; cvta.to.shared.u64 t, %1; cvt.u32.u64 %0, t; }" : "=r"(a) : "l"(p));
    return a;
}
__device__ __forceinline__ uint32_t swz(uint32_t off) {
    return off ^ ((off >> 3) & 0x70);
}
#define CP16(dst, src) \
    asm volatile("cp.async.cg.shared.global [%0], [%1], 16;" :: "r"(dst), \
                 "l"(__cvta_generic_to_global(src)))
#define CP_COMMIT() asm volatile("cp.async.commit_group;")
#define CP_WAIT1()  asm volatile("cp.async.wait_group 1;")
#define CP_WAIT0()  asm volatile("cp.async.wait_group 0;")

#define LDSM4(r0, r1, r2, r3, addr) \
    asm volatile("ldmatrix.sync.aligned.m8n8.x4.shared.b16 {%0,%1,%2,%3}, [%4];" \
        : "=r"(r0), "=r"(r1), "=r"(r2), "=r"(r3) : "r"(addr))

#define MMA16816(d, a, b0, b1) \
    asm volatile("mma.sync.aligned.m16n8k16.row.col.f32.f16.f16.f32 " \
        "{%0,%1,%2,%3},{%4,%5,%6,%7},{%8,%9},{%0,%1,%2,%3};" \
        : "+f"((d)[0]), "+f"((d)[1]), "+f"((d)[2]), "+f"((d)[3]) \
        : "r"((a)[0]), "r"((a)[1]), "r"((a)[2]), "r"((a)[3]), "r"(b0), "r"(b1))

#define STAGE 32768u

// ============================================================
// Multi-tile GEMM mainloop: 128x128 CTA tile, 8 warps (64x32), BK=64,
// 3-stage cp.async ring spanning NT consecutive M-tiles (A advances
// 128 rows per tile, B re-cycles K). Epilogue per tile is register-only
// and overlaps the next tile's in-flight loads.
// ============================================================
template<int LD, int KITERS, int NT, typename Epi>
__device__ __forceinline__ void mma_multitile(
    const __half* __restrict__ Asrc, const __half* __restrict__ Bsrc,
    uint32_t sbase, int tid, int lane, int wm, int wn, Epi epi)
{
    uint32_t dstA[4];
    const __half* srcA[4];
    const __half* srcB[4];
#pragma unroll
    for (int i = 0; i < 4; i++) {
        int u = tid + i * 256, row = u >> 3, cell = u & 7;
        dstA[i] = sbase + swz(row * 128 + cell * 16);
        srcA[i] = Asrc + (size_t)row * LD + cell * 8;
        srcB[i] = Bsrc + (size_t)row * LD + cell * 8;
    }

    const int TOT = NT * KITERS;

    // prologue: chunks 0,1
#pragma unroll
    for (int st = 0; st < 2; st++) {
        const int tile = st / KITERS, kc = st % KITERS;
        const size_t aoff = (size_t)tile * (128 * LD) + kc * 64;
        const size_t boff = (size_t)kc * 64;
        const uint32_t bo = st * STAGE;
#pragma unroll
        for (int i = 0; i < 4; i++) {
            CP16(dstA[i] + bo, srcA[i] + aoff);
            CP16(dstA[i] + 16384u + bo, srcB[i] + boff);
        }
        CP_COMMIT();
    }

    uint32_t aB[4], bB[2];
#pragma unroll
    for (int mt = 0; mt < 4; mt++) {
        int row = wm * 64 + mt * 16 + (lane & 15);
        aB[mt] = sbase + row * 128 + ((((uint32_t)row & 7) << 4) ^ (((uint32_t)lane >> 4) << 4));
    }
    {
        const int brl = ((lane >> 4) << 3) + (lane & 7);
#pragma unroll
        for (int np = 0; np < 2; np++) {
            int row = wn * 32 + np * 16 + brl;
            bB[np] = sbase + 16384 + row * 128 +
                     ((((uint32_t)row & 7) << 4) ^ ((((uint32_t)lane >> 3) & 1) << 4));
        }
    }

    float acc[4][4][4];
#pragma unroll
    for (int i = 0; i < 4; i++)
#pragma unroll
        for (int j = 0; j < 4; j++)
#pragma unroll
            for (int k = 0; k < 4; k++) acc[i][j][k] = 0.f;

#pragma unroll
    for (int ch = 0; ch < TOT; ch++) {
        if (ch < TOT - 1) { CP_WAIT1(); } else { CP_WAIT0(); }
        __syncthreads();
        if (ch + 2 < TOT) {
            const int c2 = ch + 2;
            const int tile2 = c2 / KITERS, kc2 = c2 % KITERS;
            const size_t aoff = (size_t)tile2 * (128 * LD) + kc2 * 64;
            const size_t boff = (size_t)kc2 * 64;
            const uint32_t bo2 = (uint32_t)(c2 % 3) * STAGE;
#pragma unroll
            for (int i = 0; i < 4; i++) {
                CP16(dstA[i] + bo2, srcA[i] + aoff);
                CP16(dstA[i] + 16384u + bo2, srcB[i] + boff);
            }
            CP_COMMIT();
        }
        const uint32_t bo = (uint32_t)(ch % 3) * STAGE;
        const uint32_t a0 = aB[0] + bo, a1 = aB[1] + bo, a2 = aB[2] + bo, a3 = aB[3] + bo;
        const uint32_t b0 = bB[0] + bo, b1 = bB[1] + bo;
#pragma unroll
        for (int k16 = 0; k16 < 4; k16++) {
            const uint32_t kx = (uint32_t)k16 * 32u;
            uint32_t aF[4][4];
            LDSM4(aF[0][0], aF[0][1], aF[0][2], aF[0][3], a0 ^ kx);
            LDSM4(aF[1][0], aF[1][1], aF[1][2], aF[1][3], a1 ^ kx);
            LDSM4(aF[2][0], aF[2][1], aF[2][2], aF[2][3], a2 ^ kx);
            LDSM4(aF[3][0], aF[3][1], aF[3][2], aF[3][3], a3 ^ kx);
            uint32_t bF[4][2];
            {
                uint32_t r0, r1, r2, r3;
                LDSM4(r0, r1, r2, r3, b0 ^ kx);
                bF[0][0] = r0; bF[0][1] = r1; bF[1][0] = r2; bF[1][1] = r3;
                LDSM4(r0, r1, r2, r3, b1 ^ kx);
                bF[2][0] = r0; bF[2][1] = r1; bF[3][0] = r2; bF[3][1] = r3;
            }
#pragma unroll
            for (int mt = 0; mt < 4; mt++)
#pragma unroll
                for (int nt = 0; nt < 4; nt++)
                    MMA16816(acc[mt][nt], aF[mt], bF[nt][0], bF[nt][1]);
        }
        if ((ch % KITERS) == KITERS - 1) {
            epi(ch / KITERS, acc);   // register-only; overlaps in-flight loads
#pragma unroll
            for (int i = 0; i < 4; i++)
#pragma unroll
                for (int j = 0; j < 4; j++)
#pragma unroll
                    for (int k = 0; k < 4; k++) acc[i][j][k] = 0.f;
        }
    }
}

// ============================================================
// K1: depthwise conv1d (K=9, edge pad) + channel LayerNorm -> (B,T,C) fp16
// ============================================================
#define TTILE 64
__global__ __launch_bounds__(256) void dwconv_ln_kernel(
    const float* __restrict__ x,
    const float* __restrict__ dw_w, const float* __restrict__ dw_b,
    const float* __restrict__ ln_w, const float* __restrict__ ln_b,
    int b0)
{
    extern __shared__ float sm[];
    float* xs = sm;                 // [C][73]

    const int b  = b0 + blockIdx.x / (Tt / TTILE);
    const int t0 = (blockIdx.x % (Tt / TTILE)) * TTILE;
    const int tid = threadIdx.x;
    const float* xb = x + (size_t)b * Cc * Tt;

    // zero this half's g_gx2 (BHALF*512 = 8192 floats, first 32 blocks)
    if (blockIdx.x < 32) g_gx2[b0 * Hh + blockIdx.x * 256 + tid] = 0.f;

    for (int idx = tid; idx < Cc * 72; idx += 256) {
        int c = idx / 72, i = idx % 72;
        int t = t0 + i - 4;
        t = min(max(t, 0), Tt - 1);
        xs[c * 73 + i] = xb[(size_t)c * Tt + t];
    }
    __syncthreads();

    {
        const int c = tid;
        float w[9];
#pragma unroll
        for (int k = 0; k < 9; k++) w[k] = dw_w[c * 9 + k];
        const float bias = dw_b[c];
        float* xr = &xs[c * 73];
        float buf[9];
#pragma unroll
        for (int k = 0; k < 9; k++) buf[k] = xr[k];
#pragma unroll
        for (int t = 0; t < TTILE; t++) {
            float v = bias;
#pragma unroll
            for (int k = 0; k < 9; k++) v = fmaf(buf[k], w[k], v);
#pragma unroll
            for (int k = 0; k < 8; k++) buf[k] = buf[k + 1];
            buf[8] = xr[t + 9];
            xr[t] = v;
        }
    }
    __syncthreads();

    const int warp = tid >> 5, lane = tid & 31;
    for (int tt = warp; tt < TTILE; tt += 8) {
        float sum = 0.f, sq = 0.f;
#pragma unroll
        for (int j = 0; j < 8; j++) {
            float v = xs[(lane + 32 * j) * 73 + tt];
            sum += v;
            sq = fmaf(v, v, sq);
        }
#pragma unroll
        for (int o = 16; o; o >>= 1) {
            sum += __shfl_xor_sync(0xffffffffu, sum, o);
            sq  += __shfl_xor_sync(0xffffffffu, sq, o);
        }
        const float mu   = sum * (1.f / Cc);
        const float var  = sq * (1.f / Cc) - mu * mu;
        const float rstd = rsqrtf(var + 1e-5f);
#pragma unroll
        for (int j = 0; j < 8; j++) {
            int c = lane + 32 * j;
            float v = xs[c * 73 + tt];
            xs[c * 73 + tt] = (v - mu) * rstd * ln_w[c] + ln_b[c];
        }
    }
    __syncthreads();

    __half2* out2 = (__half2*)(g_yln_h + (size_t)b * Tt * Cc + (size_t)t0 * Cc);
    for (int idx = tid; idx < (Cc / 2) * TTILE; idx += 256) {
        int t = idx >> 7, c2 = (idx & 127) * 2;
        out2[(size_t)t * (Cc / 2) + (c2 >> 1)] =
            __floats2half2_rn(xs[c2 * 73 + t], xs[(c2 + 1) * 73 + t]);
    }
}

// ============================================================
// K2: prep kernel — biasC + w1 conversion
// ============================================================
__global__ __launch_bounds__(128) void prep_kernel(
    const float* __restrict__ pw2_w, const float* __restrict__ pw2_b,
    const float* __restrict__ beta,  const float* __restrict__ pw1_w)
{
    const int c = blockIdx.x;
    const int tid = threadIdx.x;

    {
        int base = c * 512;
#pragma unroll
        for (int i = 0; i < 4; i++)
            g_w1h[base + tid + i * 128] = __float2half_rn(pw1_w[base + tid + i * 128]);
    }

    float s = 0.f;
#pragma unroll
    for (int i = 0; i < 4; i++) {
        int h = tid + i * 128;
        s = fmaf(pw2_w[c * Hh + h], beta[h], s);
    }
#pragma unroll
    for (int o = 16; o; o >>= 1) s += __shfl_xor_sync(0xffffffffu, s, o);
    __shared__ float ws[4];
    if ((tid & 31) == 0) ws[tid >> 5] = s;
    __syncthreads();
    if (tid == 0) g_biasC[c] = pw2_b[c] + ws[0] + ws[1] + ws[2] + ws[3];
}

// ============================================================
// K3: GEMM1  D[t,h] = sum_c yln[b,t,c] * w1h[h,c]  — 2 T-tiles per CTA
// ============================================================
#define SM_GEMM 98304

__global__ __launch_bounds__(256, 2) void gemm1_mma(const float* __restrict__ pw1_b, int b0)
{
    extern __shared__ __align__(128) char smem[];
    const uint32_t sbase = smem_u32(smem);
    const int tid = threadIdx.x, lane = tid & 31, w = tid >> 5;
    const int wm = w & 1, wn = w >> 1;
    const int b = b0 + blockIdx.z;
    const int mBase = blockIdx.y * 256;   // 2 tiles over T
    const int n0 = blockIdx.x * 128;      // over H

    __half* Y = g_y1_h + (size_t)b * Tt * Hh;
    const int hq = n0 + wn * 32 + 2 * (lane & 3);

    auto epi = [&](int tile, float (&acc)[4][4][4]) {
        const int m0 = mBase + tile * 128;
        float bh0, bh1;
        float sq[4][2] = {};
#pragma unroll
        for (int mt = 0; mt < 4; mt++) {
            const int t1 = m0 + wm * 64 + mt * 16 + (lane >> 2);
#pragma unroll
            for (int nt = 0; nt < 4; nt++) {
                const int h = hq + nt * 8;
                bh0 = __ldg(&pw1_b[h]);
                bh1 = __ldg(&pw1_b[h + 1]);
                float v0 = acc[mt][nt][0] + bh0;
                float v1 = acc[mt][nt][1] + bh1;
                float g0 = 0.5f * v0 * (1.0f + erff(v0 * 0.70710678118654752440f));
                float g1 = 0.5f * v1 * (1.0f + erff(v1 * 0.70710678118654752440f));
                sq[nt][0] = fmaf(g0, g0, sq[nt][0]);
                sq[nt][1] = fmaf(g1, g1, sq[nt][1]);
                *(__half2*)&Y[(size_t)t1 * Hh + h] = __floats2half2_rn(g0, g1);
                float v2 = acc[mt][nt][2] + bh0;
                float v3 = acc[mt][nt][3] + bh1;
                float g2 = 0.5f * v2 * (1.0f + erff(v2 * 0.70710678118654752440f));
                float g3 = 0.5f * v3 * (1.0f + erff(v3 * 0.70710678118654752440f));
                sq[nt][0] = fmaf(g2, g2, sq[nt][0]);
                sq[nt][1] = fmaf(g3, g3, sq[nt][1]);
                *(__half2*)&Y[(size_t)(t1 + 8) * Hh + h] = __floats2half2_rn(g2, g3);
            }
        }
#pragma unroll
        for (int nt = 0; nt < 4; nt++)
#pragma unroll
            for (int cc = 0; cc < 2; cc++) {
                float s = sq[nt][cc];
                s += __shfl_xor_sync(0xffffffffu, s, 4);
                s += __shfl_xor_sync(0xffffffffu, s, 8);
                s += __shfl_xor_sync(0xffffffffu, s, 16);
                sq[nt][cc] = s;
            }
        if (lane < 4) {
#pragma unroll
            for (int nt = 0; nt < 4; nt++) {
                atomicAdd(&g_gx2[b * Hh + hq + nt * 8],     sq[nt][0]);
                atomicAdd(&g_gx2[b * Hh + hq + nt * 8 + 1], sq[nt][1]);
            }
        }
    };

    mma_multitile<Cc, Cc / 64, 2>(
        g_yln_h + (size_t)b * Tt * Cc + (size_t)mBase * Cc,
        g_w1h + (size_t)n0 * Cc,
        sbase, tid, lane, wm, wn, epi);
}

// ============================================================
// K4: GRN scale + w2 scaling fused (batch-half)
// ============================================================
__global__ __launch_bounds__(256) void grn_w2_kernel(
    const float* __restrict__ gamma, const float* __restrict__ w2, int b0)
{
    const int b = b0 + blockIdx.x;
    const int slice = blockIdx.y;           // 0..7
    const int tid = threadIdx.x;             // 256

    __shared__ float s_sm[Hh];
    __shared__ float warpsum[8];
    __shared__ float total;

    float gx0 = sqrtf(g_gx2[b * Hh + tid * 2]);
    float gx1 = sqrtf(g_gx2[b * Hh + tid * 2 + 1]);
    float s = gx0 + gx1;
#pragma unroll
    for (int o = 16; o; o >>= 1) s += __shfl_xor_sync(0xffffffffu, s, o);
    if ((tid & 31) == 0) warpsum[tid >> 5] = s;
    __syncthreads();
    if (tid == 0) {
        float t = 0.f;
#pragma unroll
        for (int i = 0; i < 8; i++) t += warpsum[i];
        total = t;
    }
    __syncthreads();
    const float inv = 1.f / (total * (1.f / Hh) + 1e-6f);
    s_sm[tid * 2]     = 1.f + gamma[tid * 2]     * gx0 * inv;
    s_sm[tid * 2 + 1] = 1.f + gamma[tid * 2 + 1] * gx1 * inv;
    __syncthreads();

    const int base = slice * (Cc * Hh / 8);
    const float4* w4 = (const float4*)(w2 + base);
    uint2* o4 = (uint2*)(g_w2s + (size_t)b * Cc * Hh + base);
#pragma unroll 4
    for (int i = tid; i < (Cc * Hh / 8) / 4; i += 256) {
        int e = base + i * 4;
        int h = e & 511;
        float4 v = w4[i];
        __half2 lo = __floats2half2_rn(v.x * s_sm[h],     v.y * s_sm[h + 1]);
        __half2 hi = __floats2half2_rn(v.z * s_sm[h + 2], v.w * s_sm[h + 3]);
        uint2 pv;
        memcpy(&pv.x, &lo, 4);
        memcpy(&pv.y, &hi, 4);
        o4[i] = pv;
    }
}

// ============================================================
// K5: GEMM2  D[c,t] = sum_h w2s[b,c,h] * y1[b,t,h]
// 2 C-tiles per CTA (covers all of C=256)
// ============================================================
__global__ __launch_bounds__(256, 2) void gemm2_mma(
    const float* __restrict__ x, float* __restrict__ out, int b0)
{
    extern __shared__ __align__(128) char smem[];
    const uint32_t sbase = smem_u32(smem);
    const int tid = threadIdx.x, lane = tid & 31, w = tid >> 5;
    const int wm = w & 1, wn = w >> 1;
    const int b = b0 + blockIdx.z;
    const int n0 = blockIdx.x * 128;       // over T

    const float* xb = x + (size_t)b * Cc * Tt;
    float* ob = out + (size_t)b * Cc * Tt;
    const int nq = n0 + wn * 32 + 2 * (lane & 3);

    auto epi = [&](int tile, float (&acc)[4][4][4]) {
        const int m0 = tile * 128;
#pragma unroll
        for (int mt = 0; mt < 4; mt++) {
            const int r1 = m0 + wm * 64 + mt * 16 + (lane >> 2);
            const int r2 = r1 + 8;
            const float bc1 = g_biasC[r1];
            const float bc2 = g_biasC[r2];
#pragma unroll
            for (int nt = 0; nt < 4; nt++) {
                const int n = nq + nt * 8;
                size_t o1 = (size_t)r1 * Tt + n;
                size_t o2 = (size_t)r2 * Tt + n;
                float2 xv1 = *(const float2*)&xb[o1];
                float2 xv2 = *(const float2*)&xb[o2];
                float2 v1 = make_float2(acc[mt][nt][0] + bc1 + xv1.x,
                                        acc[mt][nt][1] + bc1 + xv1.y);
                float2 v2 = make_float2(acc[mt][nt][2] + bc2 + xv2.x,
                                        acc[mt][nt][3] + bc2 + xv2.y);
                *(float2*)&ob[o1] = v1;
                *(float2*)&ob[o2] = v2;
            }
        }
    };

    mma_multitile<Hh, Hh / 64, 2>(
        g_w2s + (size_t)b * Cc * Hh,
        g_y1_h + (size_t)b * Tt * Hh + (size_t)n0 * Hh,
        sbase, tid, lane, wm, wn, epi);
}

// ============================================================
extern "C" void kernel_launch(void* const* d_in, const int* in_sizes, int n_in,
                              void* d_out, int out_size)
{
    const float* x        = (const float*)d_in[0];
    const float* dw_w     = (const float*)d_in[1];
    const float* dw_b     = (const float*)d_in[2];
    const float* ln_w     = (const float*)d_in[3];
    const float* ln_b     = (const float*)d_in[4];
    const float* pw1_w    = (const float*)d_in[5];
    const float* pw1_b    = (const float*)d_in[6];
    const float* grn_gamma= (const float*)d_in[7];
    const float* grn_beta = (const float*)d_in[8];
    const float* pw2_w    = (const float*)d_in[9];
    const float* pw2_b    = (const float*)d_in[10];
    float* out = (float*)d_out;

    size_t smem1 = (size_t)(Cc * 73) * sizeof(float);
    cudaFuncSetAttribute(dwconv_ln_kernel,
                         cudaFuncAttributeMaxDynamicSharedMemorySize, (int)smem1);
    cudaFuncSetAttribute(gemm1_mma, cudaFuncAttributeMaxDynamicSharedMemorySize, SM_GEMM);
    cudaFuncSetAttribute(gemm2_mma, cudaFuncAttributeMaxDynamicSharedMemorySize, SM_GEMM);

    cudaStream_t s0 = 0, s1 = g_sp.s1;

    // prep first on s0; fork AFTER prep so both streams see w1h/biasC ready
    prep_kernel<<<Cc, 128, 0, s0>>>(pw2_w, pw2_b, grn_beta, pw1_w);
    cudaEventRecord(g_sp.eFork, s0);
    cudaStreamWaitEvent(s1, g_sp.eFork, 0);

    const int nb1 = BHALF * (Tt / TTILE);            // K1 blocks per half
    dim3 gg1(Hh / 128, Tt / 256, BHALF);             // gemm1: 2 T-tiles per CTA
    dim3 gg4(BHALF, 8);
    dim3 gg2(Tt / 128, 1, BHALF);                    // gemm2: 2 C-tiles per CTA

    // s1: K1(half1) -> gemm1(half1) -> grn(half1) -> gemm2(half1)
    dwconv_ln_kernel<<<nb1, 256, smem1, s1>>>(x, dw_w, dw_b, ln_w, ln_b, BHALF);
    gemm1_mma<<<gg1, 256, SM_GEMM, s1>>>(pw1_b, BHALF);
    grn_w2_kernel<<<gg4, 256, 0, s1>>>(grn_gamma, pw2_w, BHALF);
    gemm2_mma<<<gg2, 256, SM_GEMM, s1>>>(x, out, BHALF);
    cudaEventRecord(g_sp.eJoin, s1);

    // s0: K1(half0) -> gemm1(half0) -> grn(half0) -> gemm2(half0)
    dwconv_ln_kernel<<<nb1, 256, smem1, s0>>>(x, dw_w, dw_b, ln_w, ln_b, 0);
    gemm1_mma<<<gg1, 256, SM_GEMM, s0>>>(pw1_b, 0);
    grn_w2_kernel<<<gg4, 256, 0, s0>>>(grn_gamma, pw2_w, 0);
    gemm2_mma<<<gg2, 256, SM_GEMM, s0>>>(x, out, 0);

    // join
    cudaStreamWaitEvent(s0, g_sp.eJoin, 0);
}

// round 16
// speedup vs baseline: 1.0364x; 1.0364x over previous
#include <cuda_runtime.h>
#include <cuda_fp16.h>
#include <math.h>
#include <stdint.h>
#include <string.h>

#define Bb 32
#define Cc 256
#define Tt 4096
#define Hh 512
#define BHALF 16

// ---- scratch (static device globals; no runtime allocation) ----
__device__ __half g_yln_h[(size_t)Bb * Tt * Cc];   // conv+LN output (B,T,C) fp16
__device__ __half g_y1_h[(size_t)Bb * Tt * Hh];    // GELU(pw1) output (B,T,H) fp16
__device__ __half g_w1h[(size_t)Hh * Cc];          // pw1_w fp16
__device__ __half g_w2s[(size_t)Bb * Cc * Hh];     // pw2_w * s[b,h] fp16 per batch
__device__ float  g_gx2[Bb * Hh];                  // sum of squares per (b,h)
__device__ float  g_biasC[Cc];                     // pw2_b + pw2_w @ beta

// ---- streams/events created at load time (before harness checkpoints) ----
struct StreamPack {
    cudaStream_t s1;
    cudaEvent_t eFork, ePrep, eJoin;
    StreamPack() {
        cudaStreamCreateWithFlags(&s1, cudaStreamNonBlocking);
        cudaEventCreateWithFlags(&eFork, cudaEventDisableTiming);
        cudaEventCreateWithFlags(&ePrep, cudaEventDisableTiming);
        cudaEventCreateWithFlags(&eJoin, cudaEventDisableTiming);
    }
};
static StreamPack g_sp;

// ============================================================
// helpers
// ============================================================
__device__ __forceinline__ uint32_t smem_u32(const void* p) {
    uint32_t a;
    asm("{ .reg .u64 t; cvta.to.shared.u64 t, %1; cvt.u32.u64 %0, t; }" : "=r"(a) : "l"(p));
    return a;
}
__device__ __forceinline__ uint32_t swz(uint32_t off) {
    return off ^ ((off >> 3) & 0x70);
}
#define CP16(dst, src) \
    asm volatile("cp.async.cg.shared.global [%0], [%1], 16;" :: "r"(dst), \
                 "l"(__cvta_generic_to_global(src)))
#define CP_COMMIT() asm volatile("cp.async.commit_group;")
#define CP_WAIT1()  asm volatile("cp.async.wait_group 1;")
#define CP_WAIT0()  asm volatile("cp.async.wait_group 0;")

#define LDSM4(r0, r1, r2, r3, addr) \
    asm volatile("ldmatrix.sync.aligned.m8n8.x4.shared.b16 {%0,%1,%2,%3}, [%4];" \
        : "=r"(r0), "=r"(r1), "=r"(r2), "=r"(r3) : "r"(addr))

#define MMA16816(d, a, b0, b1) \
    asm volatile("mma.sync.aligned.m16n8k16.row.col.f32.f16.f16.f32 " \
        "{%0,%1,%2,%3},{%4,%5,%6,%7},{%8,%9},{%0,%1,%2,%3};" \
        : "+f"((d)[0]), "+f"((d)[1]), "+f"((d)[2]), "+f"((d)[3]) \
        : "r"((a)[0]), "r"((a)[1]), "r"((a)[2]), "r"((a)[3]), "r"(b0), "r"(b1))

#define STAGE 32768u

// ============================================================
// GEMM mainloop: 128x128 CTA tile, 8 warps (64x32 each), BK=64,
// 3-stage cp.async ring, one barrier per chunk,
// double-buffered fragments (R13 configuration — measured best)
// ============================================================
template<int LD, int KITERS>
__device__ __forceinline__ void mma_mainloop(
    const __half* __restrict__ Asrc, const __half* __restrict__ Bsrc,
    uint32_t sbase, int tid, int lane, int wm, int wn, float acc[4][4][4])
{
    uint32_t dstA[4];
    const __half* srcA[4];
    const ptrdiff_t dBA = Bsrc - Asrc;
#pragma unroll
    for (int i = 0; i < 4; i++) {
        int u = tid + i * 256, row = u >> 3, cell = u & 7;
        dstA[i] = sbase + swz(row * 128 + cell * 16);
        srcA[i] = Asrc + (size_t)row * LD + cell * 8;
    }

    // prologue: stages 0,1
#pragma unroll
    for (int st = 0; st < 2; st++) {
        const uint32_t bo = st * STAGE;
#pragma unroll
        for (int i = 0; i < 4; i++) {
            CP16(dstA[i] + bo, srcA[i]);
            CP16(dstA[i] + 16384u + bo, srcA[i] + dBA);
            srcA[i] += 64;
        }
        CP_COMMIT();
    }

    uint32_t aB[4], bB[2];
#pragma unroll
    for (int mt = 0; mt < 4; mt++) {
        int row = wm * 64 + mt * 16 + (lane & 15);
        aB[mt] = sbase + row * 128 + ((((uint32_t)row & 7) << 4) ^ (((uint32_t)lane >> 4) << 4));
    }
    {
        const int brl = ((lane >> 4) << 3) + (lane & 7);
#pragma unroll
        for (int np = 0; np < 2; np++) {
            int row = wn * 32 + np * 16 + brl;
            bB[np] = sbase + 16384 + row * 128 +
                     ((((uint32_t)row & 7) << 4) ^ ((((uint32_t)lane >> 3) & 1) << 4));
        }
    }

#pragma unroll
    for (int ch = 0; ch < KITERS; ch++) {
        if (ch < KITERS - 1) { CP_WAIT1(); } else { CP_WAIT0(); }
        __syncthreads();
        if (ch + 2 < KITERS) {
            const uint32_t bo2 = ((ch + 2) % 3) * STAGE;
#pragma unroll
            for (int i = 0; i < 4; i++) {
                CP16(dstA[i] + bo2, srcA[i]);
                CP16(dstA[i] + 16384u + bo2, srcA[i] + dBA);
                srcA[i] += 64;
            }
            CP_COMMIT();
        }
        const uint32_t bo = (ch % 3) * STAGE;
        const uint32_t a0 = aB[0] + bo, a1 = aB[1] + bo, a2 = aB[2] + bo, a3 = aB[3] + bo;
        const uint32_t b0 = bB[0] + bo, b1 = bB[1] + bo;

        uint32_t aF[2][4][4];
        uint32_t bF[2][4][2];
        LDSM4(aF[0][0][0], aF[0][0][1], aF[0][0][2], aF[0][0][3], a0);
        LDSM4(aF[0][1][0], aF[0][1][1], aF[0][1][2], aF[0][1][3], a1);
        LDSM4(aF[0][2][0], aF[0][2][1], aF[0][2][2], aF[0][2][3], a2);
        LDSM4(aF[0][3][0], aF[0][3][1], aF[0][3][2], aF[0][3][3], a3);
        {
            uint32_t r0, r1, r2, r3;
            LDSM4(r0, r1, r2, r3, b0);
            bF[0][0][0] = r0; bF[0][0][1] = r1; bF[0][1][0] = r2; bF[0][1][1] = r3;
            LDSM4(r0, r1, r2, r3, b1);
            bF[0][2][0] = r0; bF[0][2][1] = r1; bF[0][3][0] = r2; bF[0][3][1] = r3;
        }
#pragma unroll
        for (int k16 = 0; k16 < 4; k16++) {
            const int cur = k16 & 1, nxt = cur ^ 1;
            if (k16 < 3) {
                const uint32_t kx = (uint32_t)(k16 + 1) * 32u;
                LDSM4(aF[nxt][0][0], aF[nxt][0][1], aF[nxt][0][2], aF[nxt][0][3], a0 ^ kx);
                LDSM4(aF[nxt][1][0], aF[nxt][1][1], aF[nxt][1][2], aF[nxt][1][3], a1 ^ kx);
                LDSM4(aF[nxt][2][0], aF[nxt][2][1], aF[nxt][2][2], aF[nxt][2][3], a2 ^ kx);
                LDSM4(aF[nxt][3][0], aF[nxt][3][1], aF[nxt][3][2], aF[nxt][3][3], a3 ^ kx);
                uint32_t r0, r1, r2, r3;
                LDSM4(r0, r1, r2, r3, b0 ^ kx);
                bF[nxt][0][0] = r0; bF[nxt][0][1] = r1; bF[nxt][1][0] = r2; bF[nxt][1][1] = r3;
                LDSM4(r0, r1, r2, r3, b1 ^ kx);
                bF[nxt][2][0] = r0; bF[nxt][2][1] = r1; bF[nxt][3][0] = r2; bF[nxt][3][1] = r3;
            }
#pragma unroll
            for (int mt = 0; mt < 4; mt++)
#pragma unroll
                for (int nt = 0; nt < 4; nt++)
                    MMA16816(acc[mt][nt], aF[cur][mt], bF[cur][nt][0], bF[cur][nt][1]);
        }
    }
}

// ============================================================
// K1: depthwise conv1d (K=9, edge pad) + channel LayerNorm -> (B,T,C) fp16
// batch-half version; coalesced interior load + separate halo load
// ============================================================
#define TTILE 64
__global__ __launch_bounds__(256) void dwconv_ln_kernel(
    const float* __restrict__ x,
    const float* __restrict__ dw_w, const float* __restrict__ dw_b,
    const float* __restrict__ ln_w, const float* __restrict__ ln_b,
    int b0)
{
    extern __shared__ float sm[];
    float* xs = sm;                 // [C][73]  slots 0..71 data, 72 pad

    const int b  = b0 + blockIdx.x / (Tt / TTILE);
    const int t0 = (blockIdx.x % (Tt / TTILE)) * TTILE;
    const int tid = threadIdx.x;
    const float* xb = x + (size_t)b * Cc * Tt;

    // zero this half's g_gx2 (BHALF*512 = 8192 floats, first 32 blocks)
    if (blockIdx.x < 32) g_gx2[b0 * Hh + blockIdx.x * 256 + tid] = 0.f;

    // interior load: t in [t0, t0+64), fully coalesced (64-aligned rows)
    for (int idx = tid; idx < Cc * TTILE; idx += 256) {
        int c = idx >> 6, i = idx & 63;
        xs[c * 73 + 4 + i] = xb[(size_t)c * Tt + t0 + i];
    }
    // halo load: 4 left + 4 right per channel, with edge clamp
    for (int idx = tid; idx < Cc * 8; idx += 256) {
        int c = idx >> 3, j = idx & 7;
        int t, slot;
        if (j < 4) { t = t0 + j - 4;          slot = j; }
        else       { t = t0 + TTILE + (j - 4); slot = 64 + j; }   // 68..71
        t = min(max(t, 0), Tt - 1);
        xs[c * 73 + slot] = xb[(size_t)c * Tt + t];
    }
    __syncthreads();

    {
        const int c = tid;
        float w[9];
#pragma unroll
        for (int k = 0; k < 9; k++) w[k] = dw_w[c * 9 + k];
        const float bias = dw_b[c];
        float* xr = &xs[c * 73];
        float buf[9];
#pragma unroll
        for (int k = 0; k < 9; k++) buf[k] = xr[k];
#pragma unroll
        for (int t = 0; t < TTILE; t++) {
            float v = bias;
#pragma unroll
            for (int k = 0; k < 9; k++) v = fmaf(buf[k], w[k], v);
#pragma unroll
            for (int k = 0; k < 8; k++) buf[k] = buf[k + 1];
            buf[8] = xr[t + 9];     // t=63 reads pad slot 72 (unused value)
            xr[t] = v;
        }
    }
    __syncthreads();

    const int warp = tid >> 5, lane = tid & 31;
    for (int tt = warp; tt < TTILE; tt += 8) {
        float sum = 0.f, sq = 0.f;
#pragma unroll
        for (int j = 0; j < 8; j++) {
            float v = xs[(lane + 32 * j) * 73 + tt];
            sum += v;
            sq = fmaf(v, v, sq);
        }
#pragma unroll
        for (int o = 16; o; o >>= 1) {
            sum += __shfl_xor_sync(0xffffffffu, sum, o);
            sq  += __shfl_xor_sync(0xffffffffu, sq, o);
        }
        const float mu   = sum * (1.f / Cc);
        const float var  = sq * (1.f / Cc) - mu * mu;
        const float rstd = rsqrtf(var + 1e-5f);
#pragma unroll
        for (int j = 0; j < 8; j++) {
            int c = lane + 32 * j;
            float v = xs[c * 73 + tt];
            xs[c * 73 + tt] = (v - mu) * rstd * ln_w[c] + ln_b[c];
        }
    }
    __syncthreads();

    __half2* out2 = (__half2*)(g_yln_h + (size_t)b * Tt * Cc + (size_t)t0 * Cc);
    for (int idx = tid; idx < (Cc / 2) * TTILE; idx += 256) {
        int t = idx >> 7, c2 = (idx & 127) * 2;
        out2[(size_t)t * (Cc / 2) + (c2 >> 1)] =
            __floats2half2_rn(xs[c2 * 73 + t], xs[(c2 + 1) * 73 + t]);
    }
}

// ============================================================
// K2: prep kernel — biasC + w1 conversion
// ============================================================
__global__ __launch_bounds__(128) void prep_kernel(
    const float* __restrict__ pw2_w, const float* __restrict__ pw2_b,
    const float* __restrict__ beta,  const float* __restrict__ pw1_w)
{
    const int c = blockIdx.x;
    const int tid = threadIdx.x;

    {
        int base = c * 512;
#pragma unroll
        for (int i = 0; i < 4; i++)
            g_w1h[base + tid + i * 128] = __float2half_rn(pw1_w[base + tid + i * 128]);
    }

    float s = 0.f;
#pragma unroll
    for (int i = 0; i < 4; i++) {
        int h = tid + i * 128;
        s = fmaf(pw2_w[c * Hh + h], beta[h], s);
    }
#pragma unroll
    for (int o = 16; o; o >>= 1) s += __shfl_xor_sync(0xffffffffu, s, o);
    __shared__ float ws[4];
    if ((tid & 31) == 0) ws[tid >> 5] = s;
    __syncthreads();
    if (tid == 0) g_biasC[c] = pw2_b[c] + ws[0] + ws[1] + ws[2] + ws[3];
}

// ============================================================
// K3: GEMM1  D[t,h] = sum_c yln[b,t,c] * w1h[h,c]
// ============================================================
#define SM_GEMM 98304

__global__ __launch_bounds__(256, 2) void gemm1_mma(const float* __restrict__ pw1_b, int b0)
{
    extern __shared__ __align__(128) char smem[];
    const uint32_t sbase = smem_u32(smem);
    const int tid = threadIdx.x, lane = tid & 31, w = tid >> 5;
    const int wm = w & 1, wn = w >> 1;
    const int b = b0 + blockIdx.z;
    const int m0 = blockIdx.y * 128;   // over T
    const int n0 = blockIdx.x * 128;   // over H

    float acc[4][4][4];
#pragma unroll
    for (int i = 0; i < 4; i++)
#pragma unroll
        for (int j = 0; j < 4; j++)
#pragma unroll
            for (int k = 0; k < 4; k++) acc[i][j][k] = 0.f;

    mma_mainloop<Cc, Cc / 64>(
        g_yln_h + (size_t)b * Tt * Cc + (size_t)m0 * Cc,
        g_w1h + (size_t)n0 * Cc,
        sbase, tid, lane, wm, wn, acc);

    __half* Y = g_y1_h + (size_t)b * Tt * Hh;
    const int hq = n0 + wn * 32 + 2 * (lane & 3);
    float bh[4][2];
#pragma unroll
    for (int nt = 0; nt < 4; nt++) {
        bh[nt][0] = __ldg(&pw1_b[hq + nt * 8]);
        bh[nt][1] = __ldg(&pw1_b[hq + nt * 8 + 1]);
    }
    float sq[4][2] = {};
#pragma unroll
    for (int mt = 0; mt < 4; mt++) {
        const int t1 = m0 + wm * 64 + mt * 16 + (lane >> 2);
#pragma unroll
        for (int nt = 0; nt < 4; nt++) {
            const int h = hq + nt * 8;
            float v0 = acc[mt][nt][0] + bh[nt][0];
            float v1 = acc[mt][nt][1] + bh[nt][1];
            float g0 = 0.5f * v0 * (1.0f + erff(v0 * 0.70710678118654752440f));
            float g1 = 0.5f * v1 * (1.0f + erff(v1 * 0.70710678118654752440f));
            sq[nt][0] = fmaf(g0, g0, sq[nt][0]);
            sq[nt][1] = fmaf(g1, g1, sq[nt][1]);
            *(__half2*)&Y[(size_t)t1 * Hh + h] = __floats2half2_rn(g0, g1);
            float v2 = acc[mt][nt][2] + bh[nt][0];
            float v3 = acc[mt][nt][3] + bh[nt][1];
            float g2 = 0.5f * v2 * (1.0f + erff(v2 * 0.70710678118654752440f));
            float g3 = 0.5f * v3 * (1.0f + erff(v3 * 0.70710678118654752440f));
            sq[nt][0] = fmaf(g2, g2, sq[nt][0]);
            sq[nt][1] = fmaf(g3, g3, sq[nt][1]);
            *(__half2*)&Y[(size_t)(t1 + 8) * Hh + h] = __floats2half2_rn(g2, g3);
        }
    }
#pragma unroll
    for (int nt = 0; nt < 4; nt++)
#pragma unroll
        for (int cc = 0; cc < 2; cc++) {
            float s = sq[nt][cc];
            s += __shfl_xor_sync(0xffffffffu, s, 4);
            s += __shfl_xor_sync(0xffffffffu, s, 8);
            s += __shfl_xor_sync(0xffffffffu, s, 16);
            sq[nt][cc] = s;
        }
    if (lane < 4) {
#pragma unroll
        for (int nt = 0; nt < 4; nt++) {
            atomicAdd(&g_gx2[b * Hh + hq + nt * 8],     sq[nt][0]);
            atomicAdd(&g_gx2[b * Hh + hq + nt * 8 + 1], sq[nt][1]);
        }
    }
}

// ============================================================
// K4: GRN scale + w2 scaling fused (batch-half)
// ============================================================
__global__ __launch_bounds__(256) void grn_w2_kernel(
    const float* __restrict__ gamma, const float* __restrict__ w2, int b0)
{
    const int b = b0 + blockIdx.x;
    const int slice = blockIdx.y;           // 0..7
    const int tid = threadIdx.x;             // 256

    __shared__ float s_sm[Hh];
    __shared__ float warpsum[8];
    __shared__ float total;

    float gx0 = sqrtf(g_gx2[b * Hh + tid * 2]);
    float gx1 = sqrtf(g_gx2[b * Hh + tid * 2 + 1]);
    float s = gx0 + gx1;
#pragma unroll
    for (int o = 16; o; o >>= 1) s += __shfl_xor_sync(0xffffffffu, s, o);
    if ((tid & 31) == 0) warpsum[tid >> 5] = s;
    __syncthreads();
    if (tid == 0) {
        float t = 0.f;
#pragma unroll
        for (int i = 0; i < 8; i++) t += warpsum[i];
        total = t;
    }
    __syncthreads();
    const float inv = 1.f / (total * (1.f / Hh) + 1e-6f);
    s_sm[tid * 2]     = 1.f + gamma[tid * 2]     * gx0 * inv;
    s_sm[tid * 2 + 1] = 1.f + gamma[tid * 2 + 1] * gx1 * inv;
    __syncthreads();

    const int base = slice * (Cc * Hh / 8);
    const float4* w4 = (const float4*)(w2 + base);
    uint2* o4 = (uint2*)(g_w2s + (size_t)b * Cc * Hh + base);
#pragma unroll 4
    for (int i = tid; i < (Cc * Hh / 8) / 4; i += 256) {
        int e = base + i * 4;
        int h = e & 511;
        float4 v = w4[i];
        __half2 lo = __floats2half2_rn(v.x * s_sm[h],     v.y * s_sm[h + 1]);
        __half2 hi = __floats2half2_rn(v.z * s_sm[h + 2], v.w * s_sm[h + 3]);
        uint2 pv;
        memcpy(&pv.x, &lo, 4);
        memcpy(&pv.y, &hi, 4);
        o4[i] = pv;
    }
}

// ============================================================
// K5: GEMM2  D[c,t] = sum_h w2s[b,c,h] * y1[b,t,h]
// ============================================================
__global__ __launch_bounds__(256, 2) void gemm2_mma(
    const float* __restrict__ x, float* __restrict__ out, int b0)
{
    extern __shared__ __align__(128) char smem[];
    const uint32_t sbase = smem_u32(smem);
    const int tid = threadIdx.x, lane = tid & 31, w = tid >> 5;
    const int wm = w & 1, wn = w >> 1;
    const int b = b0 + blockIdx.z, m0 = blockIdx.y * 128, n0 = blockIdx.x * 128;

    float acc[4][4][4];
#pragma unroll
    for (int i = 0; i < 4; i++)
#pragma unroll
        for (int j = 0; j < 4; j++)
#pragma unroll
            for (int k = 0; k < 4; k++) acc[i][j][k] = 0.f;

    mma_mainloop<Hh, Hh / 64>(
        g_w2s + (size_t)b * Cc * Hh + (size_t)m0 * Hh,
        g_y1_h + (size_t)b * Tt * Hh + (size_t)n0 * Hh,
        sbase, tid, lane, wm, wn, acc);

    const float* xb = x + (size_t)b * Cc * Tt;
    float* ob = out + (size_t)b * Cc * Tt;
    const int nq = n0 + wn * 32 + 2 * (lane & 3);
#pragma unroll
    for (int mt = 0; mt < 4; mt++) {
        const int r1 = m0 + wm * 64 + mt * 16 + (lane >> 2);
        const int r2 = r1 + 8;
        const float bc1 = g_biasC[r1];
        const float bc2 = g_biasC[r2];
#pragma unroll
        for (int nt = 0; nt < 4; nt++) {
            const int n = nq + nt * 8;
            size_t o1 = (size_t)r1 * Tt + n;
            size_t o2 = (size_t)r2 * Tt + n;
            float2 xv1 = *(const float2*)&xb[o1];
            float2 xv2 = *(const float2*)&xb[o2];
            float2 v1 = make_float2(acc[mt][nt][0] + bc1 + xv1.x,
                                    acc[mt][nt][1] + bc1 + xv1.y);
            float2 v2 = make_float2(acc[mt][nt][2] + bc2 + xv2.x,
                                    acc[mt][nt][3] + bc2 + xv2.y);
            *(float2*)&ob[o1] = v1;
            *(float2*)&ob[o2] = v2;
        }
    }
}

// ============================================================
extern "C" void kernel_launch(void* const* d_in, const int* in_sizes, int n_in,
                              void* d_out, int out_size)
{
    const float* x        = (const float*)d_in[0];
    const float* dw_w     = (const float*)d_in[1];
    const float* dw_b     = (const float*)d_in[2];
    const float* ln_w     = (const float*)d_in[3];
    const float* ln_b     = (const float*)d_in[4];
    const float* pw1_w    = (const float*)d_in[5];
    const float* pw1_b    = (const float*)d_in[6];
    const float* grn_gamma= (const float*)d_in[7];
    const float* grn_beta = (const float*)d_in[8];
    const float* pw2_w    = (const float*)d_in[9];
    const float* pw2_b    = (const float*)d_in[10];
    float* out = (float*)d_out;

    size_t smem1 = (size_t)(Cc * 73) * sizeof(float);
    cudaFuncSetAttribute(dwconv_ln_kernel,
                         cudaFuncAttributeMaxDynamicSharedMemorySize, (int)smem1);
    cudaFuncSetAttribute(gemm1_mma, cudaFuncAttributeMaxDynamicSharedMemorySize, SM_GEMM);
    cudaFuncSetAttribute(gemm2_mma, cudaFuncAttributeMaxDynamicSharedMemorySize, SM_GEMM);

    cudaStream_t s0 = 0, s1 = g_sp.s1;

    // fork s1 from s0 (R13 schedule)
    cudaEventRecord(g_sp.eFork, s0);
    cudaStreamWaitEvent(s1, g_sp.eFork, 0);

    const int nb1 = BHALF * (Tt / TTILE);            // K1 blocks per half
    dim3 gg1(Hh / 128, Tt / 128, BHALF);
    dim3 gg4(BHALF, 8);
    dim3 gg2(Tt / 128, Cc / 128, BHALF);

    // s1: prep -> K1(half1) -> gemm1(half1) -> grn(half1) -> gemm2(half1)
    prep_kernel<<<Cc, 128, 0, s1>>>(pw2_w, pw2_b, grn_beta, pw1_w);
    cudaEventRecord(g_sp.ePrep, s1);
    dwconv_ln_kernel<<<nb1, 256, smem1, s1>>>(x, dw_w, dw_b, ln_w, ln_b, BHALF);
    gemm1_mma<<<gg1, 256, SM_GEMM, s1>>>(pw1_b, BHALF);
    grn_w2_kernel<<<gg4, 256, 0, s1>>>(grn_gamma, pw2_w, BHALF);
    gemm2_mma<<<gg2, 256, SM_GEMM, s1>>>(x, out, BHALF);
    cudaEventRecord(g_sp.eJoin, s1);

    // s0: K1(half0) -> (wait prep) -> gemm1(half0) -> grn(half0) -> gemm2(half0)
    dwconv_ln_kernel<<<nb1, 256, smem1, s0>>>(x, dw_w, dw_b, ln_w, ln_b, 0);
    cudaStreamWaitEvent(s0, g_sp.ePrep, 0);
    gemm1_mma<<<gg1, 256, SM_GEMM, s0>>>(pw1_b, 0);
    grn_w2_kernel<<<gg4, 256, 0, s0>>>(grn_gamma, pw2_w, 0);
    gemm2_mma<<<gg2, 256, SM_GEMM, s0>>>(x, out, 0);

    // join
    cudaStreamWaitEvent(s0, g_sp.eJoin, 0);
}

// round 17
// speedup vs baseline: 1.1370x; 1.0971x over previous
#include <cuda_runtime.h>
#include <cuda_fp16.h>
#include <math.h>
#include <stdint.h>
#include <string.h>

#define Bb 32
#define Cc 256
#define Tt 4096
#define Hh 512
#define BHALF 16

// ---- scratch (static device globals; no runtime allocation) ----
__device__ __half g_yln_h[(size_t)Bb * Tt * Cc];   // conv+LN output (B,T,C) fp16
__device__ __half g_y1_h[(size_t)Bb * Tt * Hh];    // GELU(pw1) output (B,T,H) fp16
__device__ __half g_w1h[(size_t)Hh * Cc];          // pw1_w fp16
__device__ __half g_w2s[(size_t)Bb * Cc * Hh];     // pw2_w * s[b,h] fp16 per batch
__device__ float  g_gx2[Bb * Hh];                  // sum of squares per (b,h)
__device__ float  g_biasC[Cc];                     // pw2_b + pw2_w @ beta

// ---- streams/events created at load time (before harness checkpoints) ----
struct StreamPack {
    cudaStream_t s1;
    cudaEvent_t eFork, ePrep, eJoin;
    StreamPack() {
        cudaStreamCreateWithFlags(&s1, cudaStreamNonBlocking);
        cudaEventCreateWithFlags(&eFork, cudaEventDisableTiming);
        cudaEventCreateWithFlags(&ePrep, cudaEventDisableTiming);
        cudaEventCreateWithFlags(&eJoin, cudaEventDisableTiming);
    }
};
static StreamPack g_sp;

// ============================================================
// helpers
// ============================================================
__device__ __forceinline__ uint32_t smem_u32(const void* p) {
    uint32_t a;
    asm("{ .reg .u64 t; cvta.to.shared.u64 t, %1; cvt.u32.u64 %0, t; }" : "=r"(a) : "l"(p));
    return a;
}
__device__ __forceinline__ uint32_t swz(uint32_t off) {
    return off ^ ((off >> 3) & 0x70);
}
__device__ __forceinline__ float tanh_fast(float z) {
    float r;
    asm("tanh.approx.f32 %0, %1;" : "=f"(r) : "f"(z));
    return r;
}
// tanh-form GELU with HW tanh: 3 MUL + 2 FMA + 1 MUFU
__device__ __forceinline__ float gelu_fast(float v) {
    float t = v * v;
    float p = fmaf(0.035677408136300125f, t, 0.7978845608028654f);
    float z = v * p;
    float th = tanh_fast(z);
    float h = 0.5f * v;
    return fmaf(h, th, h);
}
#define CP16(dst, src) \
    asm volatile("cp.async.cg.shared.global [%0], [%1], 16;" :: "r"(dst), \
                 "l"(__cvta_generic_to_global(src)))
#define CP_COMMIT() asm volatile("cp.async.commit_group;")
#define CP_WAIT1()  asm volatile("cp.async.wait_group 1;")
#define CP_WAIT0()  asm volatile("cp.async.wait_group 0;")

#define LDSM4(r0, r1, r2, r3, addr) \
    asm volatile("ldmatrix.sync.aligned.m8n8.x4.shared.b16 {%0,%1,%2,%3}, [%4];" \
        : "=r"(r0), "=r"(r1), "=r"(r2), "=r"(r3) : "r"(addr))

#define MMA16816(d, a, b0, b1) \
    asm volatile("mma.sync.aligned.m16n8k16.row.col.f32.f16.f16.f32 " \
        "{%0,%1,%2,%3},{%4,%5,%6,%7},{%8,%9},{%0,%1,%2,%3};" \
        : "+f"((d)[0]), "+f"((d)[1]), "+f"((d)[2]), "+f"((d)[3]) \
        : "r"((a)[0]), "r"((a)[1]), "r"((a)[2]), "r"((a)[3]), "r"(b0), "r"(b1))

#define STAGE 32768u

// ============================================================
// GEMM mainloop: 128x128 CTA tile, 8 warps (64x32 each), BK=64,
// 3-stage cp.async ring, one barrier per chunk,
// double-buffered fragments (R13 configuration — measured best)
// ============================================================
template<int LD, int KITERS>
__device__ __forceinline__ void mma_mainloop(
    const __half* __restrict__ Asrc, const __half* __restrict__ Bsrc,
    uint32_t sbase, int tid, int lane, int wm, int wn, float acc[4][4][4])
{
    uint32_t dstA[4];
    const __half* srcA[4];
    const ptrdiff_t dBA = Bsrc - Asrc;
#pragma unroll
    for (int i = 0; i < 4; i++) {
        int u = tid + i * 256, row = u >> 3, cell = u & 7;
        dstA[i] = sbase + swz(row * 128 + cell * 16);
        srcA[i] = Asrc + (size_t)row * LD + cell * 8;
    }

    // prologue: stages 0,1
#pragma unroll
    for (int st = 0; st < 2; st++) {
        const uint32_t bo = st * STAGE;
#pragma unroll
        for (int i = 0; i < 4; i++) {
            CP16(dstA[i] + bo, srcA[i]);
            CP16(dstA[i] + 16384u + bo, srcA[i] + dBA);
            srcA[i] += 64;
        }
        CP_COMMIT();
    }

    uint32_t aB[4], bB[2];
#pragma unroll
    for (int mt = 0; mt < 4; mt++) {
        int row = wm * 64 + mt * 16 + (lane & 15);
        aB[mt] = sbase + row * 128 + ((((uint32_t)row & 7) << 4) ^ (((uint32_t)lane >> 4) << 4));
    }
    {
        const int brl = ((lane >> 4) << 3) + (lane & 7);
#pragma unroll
        for (int np = 0; np < 2; np++) {
            int row = wn * 32 + np * 16 + brl;
            bB[np] = sbase + 16384 + row * 128 +
                     ((((uint32_t)row & 7) << 4) ^ ((((uint32_t)lane >> 3) & 1) << 4));
        }
    }

#pragma unroll
    for (int ch = 0; ch < KITERS; ch++) {
        if (ch < KITERS - 1) { CP_WAIT1(); } else { CP_WAIT0(); }
        __syncthreads();
        if (ch + 2 < KITERS) {
            const uint32_t bo2 = ((ch + 2) % 3) * STAGE;
#pragma unroll
            for (int i = 0; i < 4; i++) {
                CP16(dstA[i] + bo2, srcA[i]);
                CP16(dstA[i] + 16384u + bo2, srcA[i] + dBA);
                srcA[i] += 64;
            }
            CP_COMMIT();
        }
        const uint32_t bo = (ch % 3) * STAGE;
        const uint32_t a0 = aB[0] + bo, a1 = aB[1] + bo, a2 = aB[2] + bo, a3 = aB[3] + bo;
        const uint32_t b0 = bB[0] + bo, b1 = bB[1] + bo;

        uint32_t aF[2][4][4];
        uint32_t bF[2][4][2];
        LDSM4(aF[0][0][0], aF[0][0][1], aF[0][0][2], aF[0][0][3], a0);
        LDSM4(aF[0][1][0], aF[0][1][1], aF[0][1][2], aF[0][1][3], a1);
        LDSM4(aF[0][2][0], aF[0][2][1], aF[0][2][2], aF[0][2][3], a2);
        LDSM4(aF[0][3][0], aF[0][3][1], aF[0][3][2], aF[0][3][3], a3);
        {
            uint32_t r0, r1, r2, r3;
            LDSM4(r0, r1, r2, r3, b0);
            bF[0][0][0] = r0; bF[0][0][1] = r1; bF[0][1][0] = r2; bF[0][1][1] = r3;
            LDSM4(r0, r1, r2, r3, b1);
            bF[0][2][0] = r0; bF[0][2][1] = r1; bF[0][3][0] = r2; bF[0][3][1] = r3;
        }
#pragma unroll
        for (int k16 = 0; k16 < 4; k16++) {
            const int cur = k16 & 1, nxt = cur ^ 1;
            if (k16 < 3) {
                const uint32_t kx = (uint32_t)(k16 + 1) * 32u;
                LDSM4(aF[nxt][0][0], aF[nxt][0][1], aF[nxt][0][2], aF[nxt][0][3], a0 ^ kx);
                LDSM4(aF[nxt][1][0], aF[nxt][1][1], aF[nxt][1][2], aF[nxt][1][3], a1 ^ kx);
                LDSM4(aF[nxt][2][0], aF[nxt][2][1], aF[nxt][2][2], aF[nxt][2][3], a2 ^ kx);
                LDSM4(aF[nxt][3][0], aF[nxt][3][1], aF[nxt][3][2], aF[nxt][3][3], a3 ^ kx);
                uint32_t r0, r1, r2, r3;
                LDSM4(r0, r1, r2, r3, b0 ^ kx);
                bF[nxt][0][0] = r0; bF[nxt][0][1] = r1; bF[nxt][1][0] = r2; bF[nxt][1][1] = r3;
                LDSM4(r0, r1, r2, r3, b1 ^ kx);
                bF[nxt][2][0] = r0; bF[nxt][2][1] = r1; bF[nxt][3][0] = r2; bF[nxt][3][1] = r3;
            }
#pragma unroll
            for (int mt = 0; mt < 4; mt++)
#pragma unroll
                for (int nt = 0; nt < 4; nt++)
                    MMA16816(acc[mt][nt], aF[cur][mt], bF[cur][nt][0], bF[cur][nt][1]);
        }
    }
}

// ============================================================
// K1: depthwise conv1d (K=9, edge pad) + channel LayerNorm -> (B,T,C) fp16
// batch-half version; coalesced interior load + separate halo load
// ============================================================
#define TTILE 64
__global__ __launch_bounds__(256) void dwconv_ln_kernel(
    const float* __restrict__ x,
    const float* __restrict__ dw_w, const float* __restrict__ dw_b,
    const float* __restrict__ ln_w, const float* __restrict__ ln_b,
    int b0)
{
    extern __shared__ float sm[];
    float* xs = sm;                 // [C][73]  slots 0..71 data, 72 pad

    const int b  = b0 + blockIdx.x / (Tt / TTILE);
    const int t0 = (blockIdx.x % (Tt / TTILE)) * TTILE;
    const int tid = threadIdx.x;
    const float* xb = x + (size_t)b * Cc * Tt;

    if (blockIdx.x < 32) g_gx2[b0 * Hh + blockIdx.x * 256 + tid] = 0.f;

    // interior load: t in [t0, t0+64), fully coalesced
    for (int idx = tid; idx < Cc * TTILE; idx += 256) {
        int c = idx >> 6, i = idx & 63;
        xs[c * 73 + 4 + i] = xb[(size_t)c * Tt + t0 + i];
    }
    // halo load: 4 left + 4 right per channel, with edge clamp
    for (int idx = tid; idx < Cc * 8; idx += 256) {
        int c = idx >> 3, j = idx & 7;
        int t, slot;
        if (j < 4) { t = t0 + j - 4;          slot = j; }
        else       { t = t0 + TTILE + (j - 4); slot = 64 + j; }
        t = min(max(t, 0), Tt - 1);
        xs[c * 73 + slot] = xb[(size_t)c * Tt + t];
    }
    __syncthreads();

    {
        const int c = tid;
        float w[9];
#pragma unroll
        for (int k = 0; k < 9; k++) w[k] = dw_w[c * 9 + k];
        const float bias = dw_b[c];
        float* xr = &xs[c * 73];
        float buf[9];
#pragma unroll
        for (int k = 0; k < 9; k++) buf[k] = xr[k];
#pragma unroll
        for (int t = 0; t < TTILE; t++) {
            float v = bias;
#pragma unroll
            for (int k = 0; k < 9; k++) v = fmaf(buf[k], w[k], v);
#pragma unroll
            for (int k = 0; k < 8; k++) buf[k] = buf[k + 1];
            buf[8] = xr[t + 9];
            xr[t] = v;
        }
    }
    __syncthreads();

    const int warp = tid >> 5, lane = tid & 31;
    for (int tt = warp; tt < TTILE; tt += 8) {
        float sum = 0.f, sq = 0.f;
#pragma unroll
        for (int j = 0; j < 8; j++) {
            float v = xs[(lane + 32 * j) * 73 + tt];
            sum += v;
            sq = fmaf(v, v, sq);
        }
#pragma unroll
        for (int o = 16; o; o >>= 1) {
            sum += __shfl_xor_sync(0xffffffffu, sum, o);
            sq  += __shfl_xor_sync(0xffffffffu, sq, o);
        }
        const float mu   = sum * (1.f / Cc);
        const float var  = sq * (1.f / Cc) - mu * mu;
        const float rstd = rsqrtf(var + 1e-5f);
#pragma unroll
        for (int j = 0; j < 8; j++) {
            int c = lane + 32 * j;
            float v = xs[c * 73 + tt];
            xs[c * 73 + tt] = (v - mu) * rstd * ln_w[c] + ln_b[c];
        }
    }
    __syncthreads();

    __half2* out2 = (__half2*)(g_yln_h + (size_t)b * Tt * Cc + (size_t)t0 * Cc);
    for (int idx = tid; idx < (Cc / 2) * TTILE; idx += 256) {
        int t = idx >> 7, c2 = (idx & 127) * 2;
        out2[(size_t)t * (Cc / 2) + (c2 >> 1)] =
            __floats2half2_rn(xs[c2 * 73 + t], xs[(c2 + 1) * 73 + t]);
    }
}

// ============================================================
// K2: prep kernel — biasC + w1 conversion
// ============================================================
__global__ __launch_bounds__(128) void prep_kernel(
    const float* __restrict__ pw2_w, const float* __restrict__ pw2_b,
    const float* __restrict__ beta,  const float* __restrict__ pw1_w)
{
    const int c = blockIdx.x;
    const int tid = threadIdx.x;

    {
        int base = c * 512;
#pragma unroll
        for (int i = 0; i < 4; i++)
            g_w1h[base + tid + i * 128] = __float2half_rn(pw1_w[base + tid + i * 128]);
    }

    float s = 0.f;
#pragma unroll
    for (int i = 0; i < 4; i++) {
        int h = tid + i * 128;
        s = fmaf(pw2_w[c * Hh + h], beta[h], s);
    }
#pragma unroll
    for (int o = 16; o; o >>= 1) s += __shfl_xor_sync(0xffffffffu, s, o);
    __shared__ float ws[4];
    if ((tid & 31) == 0) ws[tid >> 5] = s;
    __syncthreads();
    if (tid == 0) g_biasC[c] = pw2_b[c] + ws[0] + ws[1] + ws[2] + ws[3];
}

// ============================================================
// K3: GEMM1  D[t,h] = sum_c yln[b,t,c] * w1h[h,c]
//   epilogue: +bias, fast tanh-GELU, direct half2 store, col sumsq
// ============================================================
#define SM_GEMM 98304

__global__ __launch_bounds__(256, 2) void gemm1_mma(const float* __restrict__ pw1_b, int b0)
{
    extern __shared__ __align__(128) char smem[];
    const uint32_t sbase = smem_u32(smem);
    const int tid = threadIdx.x, lane = tid & 31, w = tid >> 5;
    const int wm = w & 1, wn = w >> 1;
    const int b = b0 + blockIdx.z;
    const int m0 = blockIdx.y * 128;   // over T
    const int n0 = blockIdx.x * 128;   // over H

    float acc[4][4][4];
#pragma unroll
    for (int i = 0; i < 4; i++)
#pragma unroll
        for (int j = 0; j < 4; j++)
#pragma unroll
            for (int k = 0; k < 4; k++) acc[i][j][k] = 0.f;

    mma_mainloop<Cc, Cc / 64>(
        g_yln_h + (size_t)b * Tt * Cc + (size_t)m0 * Cc,
        g_w1h + (size_t)n0 * Cc,
        sbase, tid, lane, wm, wn, acc);

    __half* Y = g_y1_h + (size_t)b * Tt * Hh;
    const int hq = n0 + wn * 32 + 2 * (lane & 3);
    float bh[4][2];
#pragma unroll
    for (int nt = 0; nt < 4; nt++) {
        bh[nt][0] = __ldg(&pw1_b[hq + nt * 8]);
        bh[nt][1] = __ldg(&pw1_b[hq + nt * 8 + 1]);
    }
    float sq[4][2] = {};
#pragma unroll
    for (int mt = 0; mt < 4; mt++) {
        const int t1 = m0 + wm * 64 + mt * 16 + (lane >> 2);
#pragma unroll
        for (int nt = 0; nt < 4; nt++) {
            const int h = hq + nt * 8;
            float g0 = gelu_fast(acc[mt][nt][0] + bh[nt][0]);
            float g1 = gelu_fast(acc[mt][nt][1] + bh[nt][1]);
            sq[nt][0] = fmaf(g0, g0, sq[nt][0]);
            sq[nt][1] = fmaf(g1, g1, sq[nt][1]);
            *(__half2*)&Y[(size_t)t1 * Hh + h] = __floats2half2_rn(g0, g1);
            float g2 = gelu_fast(acc[mt][nt][2] + bh[nt][0]);
            float g3 = gelu_fast(acc[mt][nt][3] + bh[nt][1]);
            sq[nt][0] = fmaf(g2, g2, sq[nt][0]);
            sq[nt][1] = fmaf(g3, g3, sq[nt][1]);
            *(__half2*)&Y[(size_t)(t1 + 8) * Hh + h] = __floats2half2_rn(g2, g3);
        }
    }
#pragma unroll
    for (int nt = 0; nt < 4; nt++)
#pragma unroll
        for (int cc = 0; cc < 2; cc++) {
            float s = sq[nt][cc];
            s += __shfl_xor_sync(0xffffffffu, s, 4);
            s += __shfl_xor_sync(0xffffffffu, s, 8);
            s += __shfl_xor_sync(0xffffffffu, s, 16);
            sq[nt][cc] = s;
        }
    if (lane < 4) {
#pragma unroll
        for (int nt = 0; nt < 4; nt++) {
            atomicAdd(&g_gx2[b * Hh + hq + nt * 8],     sq[nt][0]);
            atomicAdd(&g_gx2[b * Hh + hq + nt * 8 + 1], sq[nt][1]);
        }
    }
}

// ============================================================
// K4: GRN scale + w2 scaling fused (batch-half)
// ============================================================
__global__ __launch_bounds__(256) void grn_w2_kernel(
    const float* __restrict__ gamma, const float* __restrict__ w2, int b0)
{
    const int b = b0 + blockIdx.x;
    const int slice = blockIdx.y;           // 0..7
    const int tid = threadIdx.x;             // 256

    __shared__ float s_sm[Hh];
    __shared__ float warpsum[8];
    __shared__ float total;

    float gx0 = sqrtf(g_gx2[b * Hh + tid * 2]);
    float gx1 = sqrtf(g_gx2[b * Hh + tid * 2 + 1]);
    float s = gx0 + gx1;
#pragma unroll
    for (int o = 16; o; o >>= 1) s += __shfl_xor_sync(0xffffffffu, s, o);
    if ((tid & 31) == 0) warpsum[tid >> 5] = s;
    __syncthreads();
    if (tid == 0) {
        float t = 0.f;
#pragma unroll
        for (int i = 0; i < 8; i++) t += warpsum[i];
        total = t;
    }
    __syncthreads();
    const float inv = 1.f / (total * (1.f / Hh) + 1e-6f);
    s_sm[tid * 2]     = 1.f + gamma[tid * 2]     * gx0 * inv;
    s_sm[tid * 2 + 1] = 1.f + gamma[tid * 2 + 1] * gx1 * inv;
    __syncthreads();

    const int base = slice * (Cc * Hh / 8);
    const float4* w4 = (const float4*)(w2 + base);
    uint2* o4 = (uint2*)(g_w2s + (size_t)b * Cc * Hh + base);
#pragma unroll 4
    for (int i = tid; i < (Cc * Hh / 8) / 4; i += 256) {
        int e = base + i * 4;
        int h = e & 511;
        float4 v = w4[i];
        __half2 lo = __floats2half2_rn(v.x * s_sm[h],     v.y * s_sm[h + 1]);
        __half2 hi = __floats2half2_rn(v.z * s_sm[h + 2], v.w * s_sm[h + 3]);
        uint2 pv;
        memcpy(&pv.x, &lo, 4);
        memcpy(&pv.y, &hi, 4);
        o4[i] = pv;
    }
}

// ============================================================
// K5: GEMM2  D[c,t] = sum_h w2s[b,c,h] * y1[b,t,h]
// ============================================================
__global__ __launch_bounds__(256, 2) void gemm2_mma(
    const float* __restrict__ x, float* __restrict__ out, int b0)
{
    extern __shared__ __align__(128) char smem[];
    const uint32_t sbase = smem_u32(smem);
    const int tid = threadIdx.x, lane = tid & 31, w = tid >> 5;
    const int wm = w & 1, wn = w >> 1;
    const int b = b0 + blockIdx.z, m0 = blockIdx.y * 128, n0 = blockIdx.x * 128;

    float acc[4][4][4];
#pragma unroll
    for (int i = 0; i < 4; i++)
#pragma unroll
        for (int j = 0; j < 4; j++)
#pragma unroll
            for (int k = 0; k < 4; k++) acc[i][j][k] = 0.f;

    mma_mainloop<Hh, Hh / 64>(
        g_w2s + (size_t)b * Cc * Hh + (size_t)m0 * Hh,
        g_y1_h + (size_t)b * Tt * Hh + (size_t)n0 * Hh,
        sbase, tid, lane, wm, wn, acc);

    const float* xb = x + (size_t)b * Cc * Tt;
    float* ob = out + (size_t)b * Cc * Tt;
    const int nq = n0 + wn * 32 + 2 * (lane & 3);
#pragma unroll
    for (int mt = 0; mt < 4; mt++) {
        const int r1 = m0 + wm * 64 + mt * 16 + (lane >> 2);
        const int r2 = r1 + 8;
        const float bc1 = g_biasC[r1];
        const float bc2 = g_biasC[r2];
#pragma unroll
        for (int nt = 0; nt < 4; nt++) {
            const int n = nq + nt * 8;
            size_t o1 = (size_t)r1 * Tt + n;
            size_t o2 = (size_t)r2 * Tt + n;
            float2 xv1 = *(const float2*)&xb[o1];
            float2 xv2 = *(const float2*)&xb[o2];
            float2 v1 = make_float2(acc[mt][nt][0] + bc1 + xv1.x,
                                    acc[mt][nt][1] + bc1 + xv1.y);
            float2 v2 = make_float2(acc[mt][nt][2] + bc2 + xv2.x,
                                    acc[mt][nt][3] + bc2 + xv2.y);
            *(float2*)&ob[o1] = v1;
            *(float2*)&ob[o2] = v2;
        }
    }
}

// ============================================================
extern "C" void kernel_launch(void* const* d_in, const int* in_sizes, int n_in,
                              void* d_out, int out_size)
{
    const float* x        = (const float*)d_in[0];
    const float* dw_w     = (const float*)d_in[1];
    const float* dw_b     = (const float*)d_in[2];
    const float* ln_w     = (const float*)d_in[3];
    const float* ln_b     = (const float*)d_in[4];
    const float* pw1_w    = (const float*)d_in[5];
    const float* pw1_b    = (const float*)d_in[6];
    const float* grn_gamma= (const float*)d_in[7];
    const float* grn_beta = (const float*)d_in[8];
    const float* pw2_w    = (const float*)d_in[9];
    const float* pw2_b    = (const float*)d_in[10];
    float* out = (float*)d_out;

    size_t smem1 = (size_t)(Cc * 73) * sizeof(float);
    cudaFuncSetAttribute(dwconv_ln_kernel,
                         cudaFuncAttributeMaxDynamicSharedMemorySize, (int)smem1);
    cudaFuncSetAttribute(gemm1_mma, cudaFuncAttributeMaxDynamicSharedMemorySize, SM_GEMM);
    cudaFuncSetAttribute(gemm2_mma, cudaFuncAttributeMaxDynamicSharedMemorySize, SM_GEMM);

    cudaStream_t s0 = 0, s1 = g_sp.s1;

    // fork s1 from s0 (R13 schedule)
    cudaEventRecord(g_sp.eFork, s0);
    cudaStreamWaitEvent(s1, g_sp.eFork, 0);

    const int nb1 = BHALF * (Tt / TTILE);
    dim3 gg1(Hh / 128, Tt / 128, BHALF);
    dim3 gg4(BHALF, 8);
    dim3 gg2(Tt / 128, Cc / 128, BHALF);

    // s1: prep -> K1(half1) -> gemm1(half1) -> grn(half1) -> gemm2(half1)
    prep_kernel<<<Cc, 128, 0, s1>>>(pw2_w, pw2_b, grn_beta, pw1_w);
    cudaEventRecord(g_sp.ePrep, s1);
    dwconv_ln_kernel<<<nb1, 256, smem1, s1>>>(x, dw_w, dw_b, ln_w, ln_b, BHALF);
    gemm1_mma<<<gg1, 256, SM_GEMM, s1>>>(pw1_b, BHALF);
    grn_w2_kernel<<<gg4, 256, 0, s1>>>(grn_gamma, pw2_w, BHALF);
    gemm2_mma<<<gg2, 256, SM_GEMM, s1>>>(x, out, BHALF);
    cudaEventRecord(g_sp.eJoin, s1);

    // s0: K1(half0) -> (wait prep) -> gemm1(half0) -> grn(half0) -> gemm2(half0)
    dwconv_ln_kernel<<<nb1, 256, smem1, s0>>>(x, dw_w, dw_b, ln_w, ln_b, 0);
    cudaStreamWaitEvent(s0, g_sp.ePrep, 0);
    gemm1_mma<<<gg1, 256, SM_GEMM, s0>>>(pw1_b, 0);
    grn_w2_kernel<<<gg4, 256, 0, s0>>>(grn_gamma, pw2_w, 0);
    gemm2_mma<<<gg2, 256, SM_GEMM, s0>>>(x, out, 0);

    // join
    cudaStreamWaitEvent(s0, g_sp.eJoin, 0);
}